// round 1
// baseline (speedup 1.0000x reference)
#include <cuda_runtime.h>
#include <math.h>

#define NUM_M 8
#define DD 256
#define HH 256
#define BM 64
#define BK 32
#define NTHREADS 256

// smem layout: ~108 KB -> 2 blocks/SM (228KB carveout), needs dynamic smem opt-in
struct Smem {
    float tgt[BM][HH];          // gathered out_embedding rows   (64 KB)
    float As[BM][BK];           // homo tile                     (8 KB)
    float Bs[BK][HH + 4];       // W^T tile (k-major), padded    (~33 KB)
    float bias[HH];
    float tn[BM];
    float logit[NUM_M][BM];     // logits, reused in-place for attention
};

__device__ __forceinline__ float fast_tanh(float x) {
    float y;
    asm("tanh.approx.f32 %0, %1;" : "=f"(y) : "f"(x));
    return y;
}

__global__ __launch_bounds__(NTHREADS, 2)
void hete_fused_kernel(const int*   __restrict__ nodes,
                       const float* __restrict__ homo,   // [M, N, D]
                       const float* __restrict__ W,      // [H, D]
                       const float* __restrict__ bvec,   // [H]
                       const float* __restrict__ oe,     // [NODE_NUM, H]
                       float*       __restrict__ out,    // [N, D]
                       int N)
{
    extern __shared__ char smem_raw[];
    Smem& s = *reinterpret_cast<Smem*>(smem_raw);
    const int tid = threadIdx.x;
    const int n0  = blockIdx.x * BM;
    const int nv  = min(BM, N - n0);   // valid nodes in this tile

    // ---- bias into smem ----
    s.bias[tid] = bvec[tid];

    // ---- gather tgt rows (clamped for tail tile) ----
    for (int q = tid; q < BM * (HH / 4); q += NTHREADS) {
        int r  = q >> 6;             // 64 float4 per row
        int c4 = q & 63;
        int rr = (r < nv) ? r : (nv - 1);
        int row = nodes[n0 + rr];
        float4 v = reinterpret_cast<const float4*>(oe)[(size_t)row * (HH / 4) + c4];
        reinterpret_cast<float4*>(&s.tgt[r][0])[c4] = v;
    }
    __syncthreads();

    // ---- tn[r] = max(||tgt_r||, eps), 4 threads per row ----
    {
        int r    = tid >> 2;
        int part = tid & 3;
        float acc = 0.f;
        const float* trow = &s.tgt[r][part * 64];
        #pragma unroll 16
        for (int c = 0; c < 64; ++c) acc = fmaf(trow[c], trow[c], acc);
        acc += __shfl_xor_sync(0xffffffffu, acc, 1);
        acc += __shfl_xor_sync(0xffffffffu, acc, 2);
        if (part == 0) s.tn[r] = fmaxf(sqrtf(acc), 1e-8f);
    }
    __syncthreads();

    const int tx = tid & 31;   // h-group:    covers h = tx*8 .. tx*8+7
    const int ty = tid >> 5;   // node-group: covers n = ty*8 .. ty*8+7 (warp == fixed ty)

    // ================= per meta-path: GEMM + cosine epilogue =================
    for (int m = 0; m < NUM_M; ++m) {
        const float* A = homo + ((size_t)m * N + n0) * DD;

        float acc[8][8];
        #pragma unroll
        for (int i = 0; i < 8; ++i)
            #pragma unroll
            for (int j = 0; j < 8; ++j) acc[i][j] = 0.f;

        for (int kt = 0; kt < DD / BK; ++kt) {
            const int k0 = kt * BK;

            // A tile: 64 rows x 32 k  (512 float4, 2 per thread)
            #pragma unroll
            for (int l = 0; l < 2; ++l) {
                int q  = tid + l * NTHREADS;
                int r  = q >> 3;         // 8 float4 per row
                int c4 = q & 7;
                float4 v = make_float4(0.f, 0.f, 0.f, 0.f);
                if (r < nv)
                    v = reinterpret_cast<const float4*>(A + (size_t)r * DD + k0)[c4];
                reinterpret_cast<float4*>(&s.As[r][0])[c4] = v;
            }
            // B tile: W[h][k0..k0+31] transposed -> Bs[kk][h]  (2048 float4, 8/thread)
            #pragma unroll
            for (int l = 0; l < 8; ++l) {
                int q  = tid + l * NTHREADS;
                int h  = q >> 3;
                int c4 = q & 7;
                float4 v = reinterpret_cast<const float4*>(W + (size_t)h * DD + k0)[c4];
                s.Bs[c4 * 4 + 0][h] = v.x;
                s.Bs[c4 * 4 + 1][h] = v.y;
                s.Bs[c4 * 4 + 2][h] = v.z;
                s.Bs[c4 * 4 + 3][h] = v.w;
            }
            __syncthreads();

            #pragma unroll
            for (int kk = 0; kk < BK; ++kk) {
                float a[8], bb[8];
                #pragma unroll
                for (int i = 0; i < 8; ++i) a[i] = s.As[ty * 8 + i][kk];   // warp-broadcast
                float4 b0 = *reinterpret_cast<const float4*>(&s.Bs[kk][tx * 8]);
                float4 b1 = *reinterpret_cast<const float4*>(&s.Bs[kk][tx * 8 + 4]);
                bb[0] = b0.x; bb[1] = b0.y; bb[2] = b0.z; bb[3] = b0.w;
                bb[4] = b1.x; bb[5] = b1.y; bb[6] = b1.z; bb[7] = b1.w;
                #pragma unroll
                for (int i = 0; i < 8; ++i)
                    #pragma unroll
                    for (int j = 0; j < 8; ++j)
                        acc[i][j] = fmaf(a[i], bb[j], acc[i][j]);
            }
            __syncthreads();
        }

        // ---- epilogue: bias + tanh + per-node dot-with-tgt and sq-norm ----
        float num[8], sq[8];
        #pragma unroll
        for (int i = 0; i < 8; ++i) { num[i] = 0.f; sq[i] = 0.f; }
        #pragma unroll
        for (int i = 0; i < 8; ++i) {
            #pragma unroll
            for (int j = 0; j < 8; ++j) {
                float z = acc[i][j] + s.bias[tx * 8 + j];
                float h = fast_tanh(z);
                num[i] = fmaf(h, s.tgt[ty * 8 + i][tx * 8 + j], num[i]);
                sq[i]  = fmaf(h, h, sq[i]);
            }
        }
        // reduce across the 32 h-group lanes (whole warp shares ty)
        #pragma unroll
        for (int off = 16; off > 0; off >>= 1) {
            #pragma unroll
            for (int i = 0; i < 8; ++i) {
                num[i] += __shfl_xor_sync(0xffffffffu, num[i], off);
                sq[i]  += __shfl_xor_sync(0xffffffffu, sq[i],  off);
            }
        }
        if (tx == 0) {
            #pragma unroll
            for (int i = 0; i < 8; ++i) {
                int r = ty * 8 + i;
                float hn = fmaxf(sqrtf(sq[i]), 1e-8f);
                s.logit[m][r] = num[i] / (hn * s.tn[r]);
            }
        }
        // no sync needed: epilogue touches only tgt/registers; next-iter tile
        // loads are ordered by the in-loop __syncthreads before first use
    }
    __syncthreads();

    // ---- softmax over meta-paths (in place) ----
    if (tid < BM) {
        float mx = -1e30f;
        #pragma unroll
        for (int m = 0; m < NUM_M; ++m) mx = fmaxf(mx, s.logit[m][tid]);
        float e[NUM_M], sum = 0.f;
        #pragma unroll
        for (int m = 0; m < NUM_M; ++m) { e[m] = __expf(s.logit[m][tid] - mx); sum += e[m]; }
        float inv = 1.f / sum;
        #pragma unroll
        for (int m = 0; m < NUM_M; ++m) s.logit[m][tid] = e[m] * inv;
    }
    __syncthreads();

    // ---- weighted sum over meta-paths -> out[n, :]  (coalesced float4) ----
    for (int q = tid; q < BM * (DD / 4); q += NTHREADS) {
        int r  = q >> 6;
        int c4 = q & 63;
        if (r < nv) {
            float4 o = make_float4(0.f, 0.f, 0.f, 0.f);
            #pragma unroll
            for (int m = 0; m < NUM_M; ++m) {
                float a = s.logit[m][r];
                float4 v = reinterpret_cast<const float4*>(homo)
                               [((size_t)m * N + n0 + r) * (DD / 4) + c4];
                o.x = fmaf(a, v.x, o.x);
                o.y = fmaf(a, v.y, o.y);
                o.z = fmaf(a, v.z, o.z);
                o.w = fmaf(a, v.w, o.w);
            }
            reinterpret_cast<float4*>(out)[(size_t)(n0 + r) * (DD / 4) + c4] = o;
        }
    }
}

extern "C" void kernel_launch(void* const* d_in, const int* in_sizes, int n_in,
                              void* d_out, int out_size) {
    const int*   nodes = (const int*)  d_in[0];
    const float* homo  = (const float*)d_in[1];
    const float* W     = (const float*)d_in[2];
    const float* b     = (const float*)d_in[3];
    const float* oe    = (const float*)d_in[4];
    float* out = (float*)d_out;
    const int N = in_sizes[0];

    (void)n_in; (void)out_size;

    static_assert(sizeof(Smem) < 227 * 1024, "smem too big");
    cudaFuncSetAttribute(hete_fused_kernel,
                         cudaFuncAttributeMaxDynamicSharedMemorySize,
                         (int)sizeof(Smem));

    int grid = (N + BM - 1) / BM;
    hete_fused_kernel<<<grid, NTHREADS, sizeof(Smem)>>>(nodes, homo, W, b, oe, out, N);
}

// round 3
// speedup vs baseline: 3.5348x; 3.5348x over previous
#include <cuda_runtime.h>
#include <cuda_bf16.h>
#include <cstdint>

#define NUM_M 8
#define DD 256
#define HH 256
#define BM 64
#define NT 256

#define TGT_STRIDE 264   // bf16 elems per row; word-stride 132 == 4 mod 32 -> conflict-free epilogue reads

// ---- dynamic smem layout (bytes) ----
#define OFF_B     0                          // 4 ktiles x [256 rows x 128B] = 131072 (W bf16, resident)
#define OFF_A     131072                     // 4 ktiles x [64 rows x 128B]  = 32768
#define OFF_TGT   163840                     // 64 x 264 bf16 = 33792
#define OFF_BIAS  197632                     // 256 f32
#define OFF_TN    198656                     // 64 f32
#define OFF_LOGIT 198912                     // 8 x 64 f32
#define OFF_RNUM  200960                     // 64 x 4 f32
#define OFF_RSQ   201984                     // 64 x 4 f32
#define SMEM_SIZE 203008                     // ~198 KB

#define SWZ(o) ((o) ^ (((o) >> 3) & 0x70))

__device__ __forceinline__ uint32_t smem_to_u32(const void* p) {
    uint32_t a;
    asm("{ .reg .u64 t; cvta.to.shared.u64 t, %1; cvt.u32.u64 %0, t; }" : "=r"(a) : "l"(p));
    return a;
}
__device__ __forceinline__ float fast_tanh(float x) {
    float y; asm("tanh.approx.f32 %0, %1;" : "=f"(y) : "f"(x)); return y;
}
__device__ __forceinline__ uint32_t pack_bf16x2(float lo, float hi) {
    uint32_t r; asm("cvt.rn.bf16x2.f32 %0, %1, %2;" : "=r"(r) : "f"(hi), "f"(lo)); return r;
}

#define LDSM4(r, addr) \
    asm volatile("ldmatrix.sync.aligned.m8n8.x4.shared.b16 {%0,%1,%2,%3}, [%4];" \
        : "=r"((r)[0]), "=r"((r)[1]), "=r"((r)[2]), "=r"((r)[3]) : "r"(addr))

#define MMA_BF16(c, a, bv0, bv1) \
    asm volatile("mma.sync.aligned.m16n8k16.row.col.f32.bf16.bf16.f32 " \
        "{%0,%1,%2,%3}, {%4,%5,%6,%7}, {%8,%9}, {%0,%1,%2,%3};" \
        : "+f"((c)[0]), "+f"((c)[1]), "+f"((c)[2]), "+f"((c)[3]) \
        : "r"((a)[0]), "r"((a)[1]), "r"((a)[2]), "r"((a)[3]), "r"(bv0), "r"(bv1))

// Prefetch homo[m] rows for this block into registers (16 float4 / thread).
// thread t: row = t>>2 (64 rows), quarter q = t&3 -> k-tile q (64 f32).
__device__ __forceinline__ void loadA_regs(float4* pf, const float* __restrict__ homo,
                                           int m, int N, int n0, int nv, int tid) {
    const int row = tid >> 2;
    const int q   = tid & 3;
    if (row < nv) {
        const float4* src = reinterpret_cast<const float4*>(homo)
                            + ((size_t)m * N + n0 + row) * (DD / 4) + q * 16;
        #pragma unroll
        for (int j = 0; j < 16; ++j) pf[j] = src[j];
    } else {
        #pragma unroll
        for (int j = 0; j < 16; ++j) pf[j] = make_float4(0.f, 0.f, 0.f, 0.f);
    }
}

// Convert prefetched f32 -> bf16 and store into swizzled A k-tile blocks.
__device__ __forceinline__ void storeA(const float4* pf, char* smem, int tid) {
    const int row = tid >> 2;
    const int q   = tid & 3;
    const uint32_t base = (uint32_t)(q * 8192 + row * 128);
    #pragma unroll
    for (int j = 0; j < 16; ++j) {
        uint32_t off = SWZ(base + j * 8);
        uint2 v;
        v.x = pack_bf16x2(pf[j].x, pf[j].y);
        v.y = pack_bf16x2(pf[j].z, pf[j].w);
        *reinterpret_cast<uint2*>(smem + OFF_A + off) = v;
    }
}

__global__ __launch_bounds__(NT, 1)
void hete_mma_kernel(const int*   __restrict__ nodes,
                     const float* __restrict__ homo,   // [M, N, D] f32
                     const float* __restrict__ W,      // [H, D] f32
                     const float* __restrict__ bvec,   // [H]
                     const float* __restrict__ oe,     // [NODE_NUM, H]
                     float*       __restrict__ out,    // [N, D]
                     int N)
{
    extern __shared__ char smem[];
    const uint32_t sb = smem_to_u32(smem);
    const int tid  = threadIdx.x;
    const int lane = tid & 31;
    const int wid  = tid >> 5;
    const int wm   = wid & 1;    // warp row group: rows wm*32 .. +31
    const int wn   = wid >> 1;   // warp col group: cols wn*64 .. +63
    const int n0   = blockIdx.x * BM;
    const int nv   = min(BM, N - n0);

    float* sbias  = (float*)(smem + OFF_BIAS);
    float* stn    = (float*)(smem + OFF_TN);
    float* slogit = (float*)(smem + OFF_LOGIT);
    float* srnum  = (float*)(smem + OFF_RNUM);   // [64][4]
    float* srsq   = (float*)(smem + OFF_RSQ);    // [64][4]

    // ---------------- init phase ----------------
    sbias[tid] = bvec[tid];   // NT == HH

    // gather tgt rows -> bf16 (row stride 264 bf16)
    for (int q = tid; q < BM * (HH / 4); q += NT) {
        int r  = q >> 6;
        int c4 = q & 63;
        int rr = (r < nv) ? r : (nv - 1);
        int row = nodes[n0 + rr];
        float4 v = reinterpret_cast<const float4*>(oe)[(size_t)row * (HH / 4) + c4];
        uint2 p;
        p.x = pack_bf16x2(v.x, v.y);
        p.y = pack_bf16x2(v.z, v.w);
        *reinterpret_cast<uint2*>(smem + OFF_TGT + (size_t)r * (TGT_STRIDE * 2) + c4 * 8) = p;
    }

    // W -> bf16 resident B: 4 k-tile blocks of [256 rows x 128B], SW128 swizzle
    for (int q = tid; q < HH * (DD / 4); q += NT) {
        int h  = q >> 6;
        int c4 = q & 63;              // float4 index in row; k = c4*4
        float4 v = reinterpret_cast<const float4*>(W)[(size_t)h * (DD / 4) + c4];
        int ktile = c4 >> 4;          // k/64
        uint32_t off = SWZ((uint32_t)(h * 128 + (c4 & 15) * 8));
        uint2 p;
        p.x = pack_bf16x2(v.x, v.y);
        p.y = pack_bf16x2(v.z, v.w);
        *reinterpret_cast<uint2*>(smem + OFF_B + ktile * 32768 + off) = p;
    }

    // A for m=0
    {
        float4 pf0[16];
        loadA_regs(pf0, homo, 0, N, n0, nv, tid);
        storeA(pf0, smem, tid);
    }
    __syncthreads();

    // tn from bf16 tgt (2 threads per row) — visible by first epilogue's sync
    if (tid < 2 * BM) {
        int r = tid >> 1, part = tid & 1;
        const __nv_bfloat162* trow = reinterpret_cast<const __nv_bfloat162*>(
            smem + OFF_TGT + (size_t)r * (TGT_STRIDE * 2)) + part * 64;
        float acc = 0.f;
        #pragma unroll 16
        for (int c = 0; c < 64; ++c) {
            float2 t = __bfloat1622float2(trow[c]);
            acc = fmaf(t.x, t.x, acc);
            acc = fmaf(t.y, t.y, acc);
        }
        acc += __shfl_xor_sync(0xffffffffu, acc, 1);
        if (part == 0) stn[r] = fmaxf(sqrtf(acc), 1e-8f);
    }

    const int gid = lane >> 2;   // group id 0..7
    const int tig = lane & 3;    // thread-in-group
    const int rowsel = lane & 15;
    const __nv_bfloat162* tg2 = reinterpret_cast<const __nv_bfloat162*>(smem + OFF_TGT);

    // ---------------- meta-path loop ----------------
    for (int m = 0; m < NUM_M; ++m) {
        float acc[2][8][4];
        #pragma unroll
        for (int mt = 0; mt < 2; ++mt)
            #pragma unroll
            for (int nt = 0; nt < 8; ++nt)
                #pragma unroll
                for (int e = 0; e < 4; ++e) acc[mt][nt][e] = 0.f;

        #pragma unroll
        for (int ktile = 0; ktile < 4; ++ktile) {
            const uint32_t aBase = sb + OFF_A + ktile * 8192;
            const uint32_t bBase = sb + OFF_B + ktile * 32768;
            #pragma unroll
            for (int kk = 0; kk < 4; ++kk) {
                const uint32_t kb = (uint32_t)(kk * 32 + ((lane >> 4) << 4));
                uint32_t a[2][4], b[4][4];
                #pragma unroll
                for (int mt = 0; mt < 2; ++mt) {
                    uint32_t off = (uint32_t)((wm * 32 + mt * 16 + rowsel) * 128) + kb;
                    LDSM4(a[mt], aBase + SWZ(off));
                }
                #pragma unroll
                for (int np = 0; np < 4; ++np) {
                    uint32_t off = (uint32_t)((wn * 64 + np * 16 + rowsel) * 128) + kb;
                    LDSM4(b[np], bBase + SWZ(off));
                }
                #pragma unroll
                for (int mt = 0; mt < 2; ++mt)
                    #pragma unroll
                    for (int nt = 0; nt < 8; ++nt) {
                        const int np = nt >> 1, hl = nt & 1;
                        MMA_BF16(acc[mt][nt], a[mt], b[np][hl], b[np][hl + 2]);
                    }
            }
        }

        // prefetch next meta-path's A rows (gmem -> regs) to hide latency behind epilogue
        float4 pf[16];
        if (m + 1 < NUM_M) loadA_regs(pf, homo, m + 1, N, n0, nv, tid);

        // ---- epilogue on register accumulators ----
        float numr[2][2], sqr[2][2];
        #pragma unroll
        for (int mt = 0; mt < 2; ++mt)
            for (int h = 0; h < 2; ++h) { numr[mt][h] = 0.f; sqr[mt][h] = 0.f; }

        #pragma unroll
        for (int mt = 0; mt < 2; ++mt) {
            const int rowA = wm * 32 + mt * 16 + gid;
            const int rowB = rowA + 8;
            #pragma unroll
            for (int nt = 0; nt < 8; ++nt) {
                const int col = wn * 64 + nt * 8 + tig * 2;
                float2 b2 = *reinterpret_cast<const float2*>(&sbias[col]);
                float2 tA = __bfloat1622float2(tg2[rowA * (TGT_STRIDE / 2) + (col >> 1)]);
                float2 tB = __bfloat1622float2(tg2[rowB * (TGT_STRIDE / 2) + (col >> 1)]);
                float h0 = fast_tanh(acc[mt][nt][0] + b2.x);
                float h1 = fast_tanh(acc[mt][nt][1] + b2.y);
                float h2 = fast_tanh(acc[mt][nt][2] + b2.x);
                float h3 = fast_tanh(acc[mt][nt][3] + b2.y);
                numr[mt][0] = fmaf(h0, tA.x, numr[mt][0]);
                numr[mt][0] = fmaf(h1, tA.y, numr[mt][0]);
                sqr[mt][0]  = fmaf(h0, h0, sqr[mt][0]);
                sqr[mt][0]  = fmaf(h1, h1, sqr[mt][0]);
                numr[mt][1] = fmaf(h2, tB.x, numr[mt][1]);
                numr[mt][1] = fmaf(h3, tB.y, numr[mt][1]);
                sqr[mt][1]  = fmaf(h2, h2, sqr[mt][1]);
                sqr[mt][1]  = fmaf(h3, h3, sqr[mt][1]);
            }
        }
        // reduce across the 4 tig lanes
        #pragma unroll
        for (int mt = 0; mt < 2; ++mt)
            #pragma unroll
            for (int h = 0; h < 2; ++h) {
                numr[mt][h] += __shfl_xor_sync(0xffffffffu, numr[mt][h], 1);
                numr[mt][h] += __shfl_xor_sync(0xffffffffu, numr[mt][h], 2);
                sqr[mt][h]  += __shfl_xor_sync(0xffffffffu, sqr[mt][h], 1);
                sqr[mt][h]  += __shfl_xor_sync(0xffffffffu, sqr[mt][h], 2);
            }
        if (tig == 0) {
            #pragma unroll
            for (int mt = 0; mt < 2; ++mt)
                #pragma unroll
                for (int h = 0; h < 2; ++h) {
                    int row = wm * 32 + mt * 16 + h * 8 + gid;
                    srnum[row * 4 + wn] = numr[mt][h];
                    srsq[row * 4 + wn]  = sqr[mt][h];
                }
        }
        __syncthreads();   // red ready; A fully consumed by all warps

        if (tid < BM) {
            float num = srnum[tid * 4] + srnum[tid * 4 + 1]
                      + srnum[tid * 4 + 2] + srnum[tid * 4 + 3];
            float sq  = srsq[tid * 4] + srsq[tid * 4 + 1]
                      + srsq[tid * 4 + 2] + srsq[tid * 4 + 3];
            float hn = fmaxf(sqrtf(sq), 1e-8f);
            slogit[m * BM + tid] = num / (hn * stn[tid]);
        }
        if (m + 1 < NUM_M) storeA(pf, smem, tid);
        __syncthreads();   // new A visible; red free for reuse
    }

    // ---------------- softmax over meta-paths ----------------
    if (tid < BM) {
        float mx = -1e30f;
        #pragma unroll
        for (int m = 0; m < NUM_M; ++m) mx = fmaxf(mx, slogit[m * BM + tid]);
        float e[NUM_M], sum = 0.f;
        #pragma unroll
        for (int m = 0; m < NUM_M; ++m) {
            e[m] = __expf(slogit[m * BM + tid] - mx);
            sum += e[m];
        }
        float inv = 1.f / sum;
        #pragma unroll
        for (int m = 0; m < NUM_M; ++m) slogit[m * BM + tid] = e[m] * inv;
    }
    __syncthreads();

    // ---------------- weighted sum (f32) -> out ----------------
    for (int q = tid; q < BM * (DD / 4); q += NT) {
        int r  = q >> 6;
        int c4 = q & 63;
        if (r < nv) {
            float4 o = make_float4(0.f, 0.f, 0.f, 0.f);
            #pragma unroll
            for (int m = 0; m < NUM_M; ++m) {
                float a = slogit[m * BM + r];
                float4 v = reinterpret_cast<const float4*>(homo)
                               [((size_t)m * N + n0 + r) * (DD / 4) + c4];
                o.x = fmaf(a, v.x, o.x);
                o.y = fmaf(a, v.y, o.y);
                o.z = fmaf(a, v.z, o.z);
                o.w = fmaf(a, v.w, o.w);
            }
            reinterpret_cast<float4*>(out)[(size_t)(n0 + r) * (DD / 4) + c4] = o;
        }
    }
}

extern "C" void kernel_launch(void* const* d_in, const int* in_sizes, int n_in,
                              void* d_out, int out_size) {
    const int*   nodes = (const int*)  d_in[0];
    const float* homo  = (const float*)d_in[1];
    const float* W     = (const float*)d_in[2];
    const float* b     = (const float*)d_in[3];
    const float* oe    = (const float*)d_in[4];
    float* out = (float*)d_out;
    const int N = in_sizes[0];
    (void)n_in; (void)out_size;

    cudaFuncSetAttribute(hete_mma_kernel,
                         cudaFuncAttributeMaxDynamicSharedMemorySize, SMEM_SIZE);

    int grid = (N + BM - 1) / BM;
    hete_mma_kernel<<<grid, NT, SMEM_SIZE>>>(nodes, homo, W, b, oe, out, N);
}

// round 4
// speedup vs baseline: 4.2308x; 1.1969x over previous
#include <cuda_runtime.h>
#include <cuda_bf16.h>
#include <cstdint>

#define NUM_M 8
#define DD 256
#define HH 256
#define BM 64
#define NT 256

#define TGT_STRIDE 264   // bf16 elems per row; word-stride 132 -> conflict-free epilogue reads

// ---- dynamic smem layout (bytes) ----
#define OFF_B     0                          // 4 ktiles x [256 rows x 128B] = 131072 (W bf16, resident)
#define OFF_A     131072                     // 4 ktiles x [64 rows x 128B]  = 32768
#define OFF_TGT   163840                     // 64 x 264 bf16 = 33792
#define OFF_BIAS  197632                     // 256 f32
#define OFF_TN    198656                     // 64 f32
#define OFF_LOGIT 198912                     // 8 x 64 f32
#define OFF_RNUM  200960                     // 64 x 4 f32
#define OFF_RSQ   201984                     // 64 x 4 f32
#define SMEM_SIZE 203008                     // ~198 KB

#define SWZ(o) ((o) ^ (((o) >> 3) & 0x70))

__device__ __forceinline__ uint32_t smem_to_u32(const void* p) {
    uint32_t a;
    asm("{ .reg .u64 t; cvta.to.shared.u64 t, %1; cvt.u32.u64 %0, t; }" : "=r"(a) : "l"(p));
    return a;
}
__device__ __forceinline__ float fast_tanh(float x) {
    float y; asm("tanh.approx.f32 %0, %1;" : "=f"(y) : "f"(x)); return y;
}
__device__ __forceinline__ uint32_t pack_bf16x2(float lo, float hi) {
    uint32_t r; asm("cvt.rn.bf16x2.f32 %0, %1, %2;" : "=r"(r) : "f"(hi), "f"(lo)); return r;
}

#define LDSM4(r, addr) \
    asm volatile("ldmatrix.sync.aligned.m8n8.x4.shared.b16 {%0,%1,%2,%3}, [%4];" \
        : "=r"((r)[0]), "=r"((r)[1]), "=r"((r)[2]), "=r"((r)[3]) : "r"(addr))

#define MMA_BF16(c, a, bv0, bv1) \
    asm volatile("mma.sync.aligned.m16n8k16.row.col.f32.bf16.bf16.f32 " \
        "{%0,%1,%2,%3}, {%4,%5,%6,%7}, {%8,%9}, {%0,%1,%2,%3};" \
        : "+f"((c)[0]), "+f"((c)[1]), "+f"((c)[2]), "+f"((c)[3]) \
        : "r"((a)[0]), "r"((a)[1]), "r"((a)[2]), "r"((a)[3]), "r"(bv0), "r"(bv1))

// ---- linear-granule A prefetch: granule g = wid*512 + j*32 + lane ----
// lanes consecutive -> coalesced 512B per LDG wave; convert to bf16 at load.
__device__ __forceinline__ void loadA_regs(uint2* pf, const float* __restrict__ homo,
                                           int m, int N, int n0, int nv,
                                           int wid, int lane) {
    const float4* base = reinterpret_cast<const float4*>(homo)
                         + ((size_t)m * N + n0) * (DD / 4);
    const int g0 = wid * 512 + lane;
    #pragma unroll
    for (int j = 0; j < 16; ++j) {
        int g = g0 + j * 32;
        float4 v = make_float4(0.f, 0.f, 0.f, 0.f);
        if ((g >> 6) < nv) v = base[g];
        pf[j].x = pack_bf16x2(v.x, v.y);
        pf[j].y = pack_bf16x2(v.z, v.w);
    }
}

// Conflict-free store: consecutive granules -> consecutive 8B smem chunks.
__device__ __forceinline__ void storeA(const uint2* pf, char* smem, int wid, int lane) {
    const int g0 = wid * 512 + lane;
    #pragma unroll
    for (int j = 0; j < 16; ++j) {
        int g    = g0 + j * 32;
        int row  = g >> 6;
        int c4   = g & 63;
        int kt   = c4 >> 4;
        uint32_t off = SWZ((uint32_t)(row * 128 + (c4 & 15) * 8));
        *reinterpret_cast<uint2*>(smem + OFF_A + kt * 8192 + off) = pf[j];
    }
}

__global__ __launch_bounds__(NT, 1)
void hete_mma_kernel(const int*   __restrict__ nodes,
                     const float* __restrict__ homo,   // [M, N, D] f32
                     const float* __restrict__ W,      // [H, D] f32
                     const float* __restrict__ bvec,   // [H]
                     const float* __restrict__ oe,     // [NODE_NUM, H]
                     float*       __restrict__ out,    // [N, D]
                     int N)
{
    extern __shared__ char smem[];
    const uint32_t sb = smem_to_u32(smem);
    const int tid  = threadIdx.x;
    const int lane = tid & 31;
    const int wid  = tid >> 5;
    const int wm   = wid & 1;    // warp row group: rows wm*32 .. +31
    const int wn   = wid >> 1;   // warp col group: cols wn*64 .. +63
    const int n0   = blockIdx.x * BM;
    const int nv   = min(BM, N - n0);

    float* sbias  = (float*)(smem + OFF_BIAS);
    float* stn    = (float*)(smem + OFF_TN);
    float* slogit = (float*)(smem + OFF_LOGIT);
    float* srnum  = (float*)(smem + OFF_RNUM);   // [64][4]
    float* srsq   = (float*)(smem + OFF_RSQ);    // [64][4]

    // ---------------- init phase ----------------
    sbias[tid] = bvec[tid];   // NT == HH

    // gather tgt rows -> bf16 (row stride 264 bf16)
    for (int q = tid; q < BM * (HH / 4); q += NT) {
        int r  = q >> 6;
        int c4 = q & 63;
        int rr = (r < nv) ? r : (nv - 1);
        int row = nodes[n0 + rr];
        float4 v = reinterpret_cast<const float4*>(oe)[(size_t)row * (HH / 4) + c4];
        uint2 p;
        p.x = pack_bf16x2(v.x, v.y);
        p.y = pack_bf16x2(v.z, v.w);
        *reinterpret_cast<uint2*>(smem + OFF_TGT + (size_t)r * (TGT_STRIDE * 2) + c4 * 8) = p;
    }

    // W -> bf16 resident B: 4 k-tile blocks of [256 rows x 128B], SW128 swizzle
    for (int q = tid; q < HH * (DD / 4); q += NT) {
        int h  = q >> 6;
        int c4 = q & 63;
        float4 v = reinterpret_cast<const float4*>(W)[(size_t)h * (DD / 4) + c4];
        int ktile = c4 >> 4;
        uint32_t off = SWZ((uint32_t)(h * 128 + (c4 & 15) * 8));
        uint2 p;
        p.x = pack_bf16x2(v.x, v.y);
        p.y = pack_bf16x2(v.z, v.w);
        *reinterpret_cast<uint2*>(smem + OFF_B + ktile * 32768 + off) = p;
    }

    // A for m=0
    {
        uint2 pf0[16];
        loadA_regs(pf0, homo, 0, N, n0, nv, wid, lane);
        storeA(pf0, smem, wid, lane);
    }
    __syncthreads();

    // tn from bf16 tgt (2 threads per row)
    if (tid < 2 * BM) {
        int r = tid >> 1, part = tid & 1;
        const __nv_bfloat162* trow = reinterpret_cast<const __nv_bfloat162*>(
            smem + OFF_TGT + (size_t)r * (TGT_STRIDE * 2)) + part * 64;
        float acc = 0.f;
        #pragma unroll 16
        for (int c = 0; c < 64; ++c) {
            float2 t = __bfloat1622float2(trow[c]);
            acc = fmaf(t.x, t.x, acc);
            acc = fmaf(t.y, t.y, acc);
        }
        acc += __shfl_xor_sync(0xffffffffu, acc, 1);
        if (part == 0) stn[r] = fmaxf(sqrtf(acc), 1e-8f);
    }

    const int gid = lane >> 2;
    const int tig = lane & 3;
    const int rowsel = lane & 15;
    const uint32_t kbsel = (uint32_t)((lane >> 4) << 4);
    const __nv_bfloat162* tg2 = reinterpret_cast<const __nv_bfloat162*>(smem + OFF_TGT);

    // precomputed swizzled LDSM offsets (k-invariant parts)
    uint32_t aOff[2], bOff[4];
    #pragma unroll
    for (int mt = 0; mt < 2; ++mt)
        aOff[mt] = (uint32_t)((wm * 32 + mt * 16 + rowsel) * 128);
    #pragma unroll
    for (int np = 0; np < 4; ++np)
        bOff[np] = (uint32_t)((wn * 64 + np * 16 + rowsel) * 128);

    // ---------------- meta-path loop ----------------
    for (int m = 0; m < NUM_M; ++m) {
        float acc[2][8][4];
        #pragma unroll
        for (int mt = 0; mt < 2; ++mt)
            #pragma unroll
            for (int nt = 0; nt < 8; ++nt)
                #pragma unroll
                for (int e = 0; e < 4; ++e) acc[mt][nt][e] = 0.f;

        // register double-buffered LDSM pipeline over 16 k-steps
        uint32_t a[2][2][4], b[2][4][4];
        {
            const uint32_t kb = kbsel;                    // kstep 0: ktile 0, kk 0
            const uint32_t aB = sb + OFF_A;
            const uint32_t bB = sb + OFF_B;
            #pragma unroll
            for (int mt = 0; mt < 2; ++mt) LDSM4(a[0][mt], aB + SWZ(aOff[mt] + kb));
            #pragma unroll
            for (int np = 0; np < 4; ++np) LDSM4(b[0][np], bB + SWZ(bOff[np] + kb));
        }

        #pragma unroll
        for (int ks = 0; ks < 16; ++ks) {
            const int cur = ks & 1;
            if (ks < 15) {
                const int nks   = ks + 1;
                const int nxt   = nks & 1;
                const uint32_t kb = (uint32_t)((nks & 3) * 32) + kbsel;
                const uint32_t aB = sb + OFF_A + (nks >> 2) * 8192;
                const uint32_t bB = sb + OFF_B + (nks >> 2) * 32768;
                #pragma unroll
                for (int mt = 0; mt < 2; ++mt) LDSM4(a[nxt][mt], aB + SWZ(aOff[mt] + kb));
                #pragma unroll
                for (int np = 0; np < 4; ++np) LDSM4(b[nxt][np], bB + SWZ(bOff[np] + kb));
            }
            #pragma unroll
            for (int mt = 0; mt < 2; ++mt)
                #pragma unroll
                for (int nt = 0; nt < 8; ++nt) {
                    const int np = nt >> 1, hl = nt & 1;
                    MMA_BF16(acc[mt][nt], a[cur][mt], b[cur][np][hl], b[cur][np][hl + 2]);
                }
        }

        // prefetch next meta-path's A (coalesced) to hide DRAM behind epilogue
        uint2 pf[16];
        if (m + 1 < NUM_M) loadA_regs(pf, homo, m + 1, N, n0, nv, wid, lane);

        // ---- epilogue on register accumulators ----
        float numr[2][2], sqr[2][2];
        #pragma unroll
        for (int mt = 0; mt < 2; ++mt)
            for (int h = 0; h < 2; ++h) { numr[mt][h] = 0.f; sqr[mt][h] = 0.f; }

        #pragma unroll
        for (int mt = 0; mt < 2; ++mt) {
            const int rowA = wm * 32 + mt * 16 + gid;
            const int rowB = rowA + 8;
            #pragma unroll
            for (int nt = 0; nt < 8; ++nt) {
                const int col = wn * 64 + nt * 8 + tig * 2;
                float2 b2 = *reinterpret_cast<const float2*>(&sbias[col]);
                float2 tA = __bfloat1622float2(tg2[rowA * (TGT_STRIDE / 2) + (col >> 1)]);
                float2 tB = __bfloat1622float2(tg2[rowB * (TGT_STRIDE / 2) + (col >> 1)]);
                float h0 = fast_tanh(acc[mt][nt][0] + b2.x);
                float h1 = fast_tanh(acc[mt][nt][1] + b2.y);
                float h2 = fast_tanh(acc[mt][nt][2] + b2.x);
                float h3 = fast_tanh(acc[mt][nt][3] + b2.y);
                numr[mt][0] = fmaf(h0, tA.x, numr[mt][0]);
                numr[mt][0] = fmaf(h1, tA.y, numr[mt][0]);
                sqr[mt][0]  = fmaf(h0, h0, sqr[mt][0]);
                sqr[mt][0]  = fmaf(h1, h1, sqr[mt][0]);
                numr[mt][1] = fmaf(h2, tB.x, numr[mt][1]);
                numr[mt][1] = fmaf(h3, tB.y, numr[mt][1]);
                sqr[mt][1]  = fmaf(h2, h2, sqr[mt][1]);
                sqr[mt][1]  = fmaf(h3, h3, sqr[mt][1]);
            }
        }
        #pragma unroll
        for (int mt = 0; mt < 2; ++mt)
            #pragma unroll
            for (int h = 0; h < 2; ++h) {
                numr[mt][h] += __shfl_xor_sync(0xffffffffu, numr[mt][h], 1);
                numr[mt][h] += __shfl_xor_sync(0xffffffffu, numr[mt][h], 2);
                sqr[mt][h]  += __shfl_xor_sync(0xffffffffu, sqr[mt][h], 1);
                sqr[mt][h]  += __shfl_xor_sync(0xffffffffu, sqr[mt][h], 2);
            }
        if (tig == 0) {
            #pragma unroll
            for (int mt = 0; mt < 2; ++mt)
                #pragma unroll
                for (int h = 0; h < 2; ++h) {
                    int row = wm * 32 + mt * 16 + h * 8 + gid;
                    srnum[row * 4 + wn] = numr[mt][h];
                    srsq[row * 4 + wn]  = sqr[mt][h];
                }
        }
        __syncthreads();   // A reads done by all warps; reductions visible

        if (m + 1 < NUM_M) storeA(pf, smem, wid, lane);
        if (tid < BM) {
            float num = srnum[tid * 4] + srnum[tid * 4 + 1]
                      + srnum[tid * 4 + 2] + srnum[tid * 4 + 3];
            float sq  = srsq[tid * 4] + srsq[tid * 4 + 1]
                      + srsq[tid * 4 + 2] + srsq[tid * 4 + 3];
            float hn = fmaxf(sqrtf(sq), 1e-8f);
            slogit[m * BM + tid] = num / (hn * stn[tid]);
        }
        __syncthreads();   // new A visible; red arrays free
    }

    // ---------------- softmax over meta-paths ----------------
    if (tid < BM) {
        float mx = -1e30f;
        #pragma unroll
        for (int m = 0; m < NUM_M; ++m) mx = fmaxf(mx, slogit[m * BM + tid]);
        float e[NUM_M], sum = 0.f;
        #pragma unroll
        for (int m = 0; m < NUM_M; ++m) {
            e[m] = __expf(slogit[m * BM + tid] - mx);
            sum += e[m];
        }
        float inv = 1.f / sum;
        #pragma unroll
        for (int m = 0; m < NUM_M; ++m) slogit[m * BM + tid] = e[m] * inv;
    }
    __syncthreads();

    // ---------------- weighted sum (f32) -> out ----------------
    for (int q = tid; q < BM * (DD / 4); q += NT) {
        int r  = q >> 6;
        int c4 = q & 63;
        if (r < nv) {
            float4 o = make_float4(0.f, 0.f, 0.f, 0.f);
            #pragma unroll
            for (int m = 0; m < NUM_M; ++m) {
                float a = slogit[m * BM + r];
                float4 v = reinterpret_cast<const float4*>(homo)
                               [((size_t)m * N + n0 + r) * (DD / 4) + c4];
                o.x = fmaf(a, v.x, o.x);
                o.y = fmaf(a, v.y, o.y);
                o.z = fmaf(a, v.z, o.z);
                o.w = fmaf(a, v.w, o.w);
            }
            reinterpret_cast<float4*>(out)[(size_t)(n0 + r) * (DD / 4) + c4] = o;
        }
    }
}

extern "C" void kernel_launch(void* const* d_in, const int* in_sizes, int n_in,
                              void* d_out, int out_size) {
    const int*   nodes = (const int*)  d_in[0];
    const float* homo  = (const float*)d_in[1];
    const float* W     = (const float*)d_in[2];
    const float* b     = (const float*)d_in[3];
    const float* oe    = (const float*)d_in[4];
    float* out = (float*)d_out;
    const int N = in_sizes[0];
    (void)n_in; (void)out_size;

    cudaFuncSetAttribute(hete_mma_kernel,
                         cudaFuncAttributeMaxDynamicSharedMemorySize, SMEM_SIZE);

    int grid = (N + BM - 1) / BM;
    hete_mma_kernel<<<grid, NT, SMEM_SIZE>>>(nodes, homo, W, b, oe, out, N);
}

// round 5
// speedup vs baseline: 4.9370x; 1.1669x over previous
#include <cuda_runtime.h>
#include <cuda_bf16.h>
#include <cstdint>

#define NUM_M 8
#define DD 256
#define HH 256
#define BM 64
#define NT 512

#define TGT_STRIDE 264   // bf16 elems per row; word-stride 132 -> conflict-free epilogue reads

// ---- dynamic smem layout (bytes) ----
#define OFF_B     0                          // 4 ktiles x [256 rows x 128B] = 131072 (W bf16, resident)
#define OFF_A     131072                     // 4 ktiles x [64 rows x 128B]  = 32768
#define OFF_TGT   163840                     // 64 x 264 bf16 = 33792
#define OFF_BIAS  197632                     // 256 f32
#define OFF_TN    198656                     // 64 f32
#define OFF_LOGIT 198912                     // 8 x 64 f32
#define OFF_RNUM  200960                     // 64 x 8 f32
#define OFF_RSQ   203008                     // 64 x 8 f32
#define SMEM_SIZE 205056                     // ~200 KB

#define SWZ(o) ((o) ^ (((o) >> 3) & 0x70))

__device__ __forceinline__ uint32_t smem_to_u32(const void* p) {
    uint32_t a;
    asm("{ .reg .u64 t; cvta.to.shared.u64 t, %1; cvt.u32.u64 %0, t; }" : "=r"(a) : "l"(p));
    return a;
}
__device__ __forceinline__ float fast_tanh(float x) {
    float y; asm("tanh.approx.f32 %0, %1;" : "=f"(y) : "f"(x)); return y;
}
__device__ __forceinline__ uint32_t pack_bf16x2(float lo, float hi) {
    uint32_t r; asm("cvt.rn.bf16x2.f32 %0, %1, %2;" : "=r"(r) : "f"(hi), "f"(lo)); return r;
}

#define LDSM4(r, addr) \
    asm volatile("ldmatrix.sync.aligned.m8n8.x4.shared.b16 {%0,%1,%2,%3}, [%4];" \
        : "=r"((r)[0]), "=r"((r)[1]), "=r"((r)[2]), "=r"((r)[3]) : "r"(addr))

#define MMA_BF16(c, a, bv0, bv1) \
    asm volatile("mma.sync.aligned.m16n8k16.row.col.f32.bf16.bf16.f32 " \
        "{%0,%1,%2,%3}, {%4,%5,%6,%7}, {%8,%9}, {%0,%1,%2,%3};" \
        : "+f"((c)[0]), "+f"((c)[1]), "+f"((c)[2]), "+f"((c)[3]) \
        : "r"((a)[0]), "r"((a)[1]), "r"((a)[2]), "r"((a)[3]), "r"(bv0), "r"(bv1))

// ---- linear-granule A prefetch: granule g = wid*256 + j*32 + lane ----
__device__ __forceinline__ void loadA_regs(uint2* pf, const float* __restrict__ homo,
                                           int m, int N, int n0, int nv,
                                           int wid, int lane) {
    const float4* base = reinterpret_cast<const float4*>(homo)
                         + ((size_t)m * N + n0) * (DD / 4);
    const int g0 = wid * 256 + lane;
    #pragma unroll
    for (int j = 0; j < 8; ++j) {
        int g = g0 + j * 32;
        float4 v = make_float4(0.f, 0.f, 0.f, 0.f);
        if ((g >> 6) < nv) v = base[g];
        pf[j].x = pack_bf16x2(v.x, v.y);
        pf[j].y = pack_bf16x2(v.z, v.w);
    }
}

__device__ __forceinline__ void storeA(const uint2* pf, char* smem, int wid, int lane) {
    const int g0 = wid * 256 + lane;
    #pragma unroll
    for (int j = 0; j < 8; ++j) {
        int g    = g0 + j * 32;
        int row  = g >> 6;
        int c4   = g & 63;
        int kt   = c4 >> 4;
        uint32_t off = SWZ((uint32_t)(row * 128 + (c4 & 15) * 8));
        *reinterpret_cast<uint2*>(smem + OFF_A + kt * 8192 + off) = pf[j];
    }
}

__global__ __launch_bounds__(NT, 1)
void hete_mma_kernel(const int*   __restrict__ nodes,
                     const float* __restrict__ homo,   // [M, N, D] f32
                     const float* __restrict__ W,      // [H, D] f32
                     const float* __restrict__ bvec,   // [H]
                     const float* __restrict__ oe,     // [NODE_NUM, H]
                     float*       __restrict__ out,    // [N, D]
                     int N)
{
    extern __shared__ char smem[];
    const uint32_t sb = smem_to_u32(smem);
    const int tid  = threadIdx.x;
    const int lane = tid & 31;
    const int wid  = tid >> 5;
    const int wm   = wid & 1;    // warp row group: rows wm*32 .. +31
    const int wn   = wid >> 1;   // warp col group: cols wn*32 .. +31
    const int n0   = blockIdx.x * BM;
    const int nv   = min(BM, N - n0);

    float* sbias  = (float*)(smem + OFF_BIAS);
    float* stn    = (float*)(smem + OFF_TN);
    float* slogit = (float*)(smem + OFF_LOGIT);
    float* srnum  = (float*)(smem + OFF_RNUM);   // [64][8]
    float* srsq   = (float*)(smem + OFF_RSQ);    // [64][8]

    // ---------------- init phase ----------------
    if (tid < HH) sbias[tid] = bvec[tid];

    // gather tgt rows -> bf16 (row stride 264 bf16)
    for (int q = tid; q < BM * (HH / 4); q += NT) {
        int r  = q >> 6;
        int c4 = q & 63;
        int rr = (r < nv) ? r : (nv - 1);
        int row = nodes[n0 + rr];
        float4 v = reinterpret_cast<const float4*>(oe)[(size_t)row * (HH / 4) + c4];
        uint2 p;
        p.x = pack_bf16x2(v.x, v.y);
        p.y = pack_bf16x2(v.z, v.w);
        *reinterpret_cast<uint2*>(smem + OFF_TGT + (size_t)r * (TGT_STRIDE * 2) + c4 * 8) = p;
    }

    // W -> bf16 resident B: 4 k-tile blocks of [256 rows x 128B], SW128 swizzle
    for (int q = tid; q < HH * (DD / 4); q += NT) {
        int h  = q >> 6;
        int c4 = q & 63;
        float4 v = reinterpret_cast<const float4*>(W)[(size_t)h * (DD / 4) + c4];
        int ktile = c4 >> 4;
        uint32_t off = SWZ((uint32_t)(h * 128 + (c4 & 15) * 8));
        uint2 p;
        p.x = pack_bf16x2(v.x, v.y);
        p.y = pack_bf16x2(v.z, v.w);
        *reinterpret_cast<uint2*>(smem + OFF_B + ktile * 32768 + off) = p;
    }

    // A for m=0
    {
        uint2 pf0[8];
        loadA_regs(pf0, homo, 0, N, n0, nv, wid, lane);
        storeA(pf0, smem, wid, lane);
    }
    __syncthreads();

    // tn from bf16 tgt (2 threads per row)
    if (tid < 2 * BM) {
        int r = tid >> 1, part = tid & 1;
        const __nv_bfloat162* trow = reinterpret_cast<const __nv_bfloat162*>(
            smem + OFF_TGT + (size_t)r * (TGT_STRIDE * 2)) + part * 64;
        float acc = 0.f;
        #pragma unroll 16
        for (int c = 0; c < 64; ++c) {
            float2 t = __bfloat1622float2(trow[c]);
            acc = fmaf(t.x, t.x, acc);
            acc = fmaf(t.y, t.y, acc);
        }
        acc += __shfl_xor_sync(0xffffffffu, acc, 1);
        if (part == 0) stn[r] = fmaxf(sqrtf(acc), 1e-8f);
    }

    const int gid = lane >> 2;
    const int tig = lane & 3;
    const int rowsel = lane & 15;
    const uint32_t kbsel = (uint32_t)((lane >> 4) << 4);
    const __nv_bfloat162* tg2 = reinterpret_cast<const __nv_bfloat162*>(smem + OFF_TGT);

    // precomputed LDSM row offsets (k-invariant parts)
    uint32_t aOff[2], bOff[2];
    #pragma unroll
    for (int mt = 0; mt < 2; ++mt)
        aOff[mt] = (uint32_t)((wm * 32 + mt * 16 + rowsel) * 128);
    #pragma unroll
    for (int np = 0; np < 2; ++np)
        bOff[np] = (uint32_t)((wn * 32 + np * 16 + rowsel) * 128);

    // ---------------- meta-path loop ----------------
    for (int m = 0; m < NUM_M; ++m) {
        float acc[2][4][4];
        #pragma unroll
        for (int mt = 0; mt < 2; ++mt)
            #pragma unroll
            for (int nt = 0; nt < 4; ++nt)
                #pragma unroll
                for (int e = 0; e < 4; ++e) acc[mt][nt][e] = 0.f;

        // register double-buffered LDSM pipeline over 16 k-steps
        uint32_t a[2][2][4], b[2][2][4];
        {
            const uint32_t kb = kbsel;
            const uint32_t aB = sb + OFF_A;
            const uint32_t bB = sb + OFF_B;
            #pragma unroll
            for (int mt = 0; mt < 2; ++mt) LDSM4(a[0][mt], aB + SWZ(aOff[mt] + kb));
            #pragma unroll
            for (int np = 0; np < 2; ++np) LDSM4(b[0][np], bB + SWZ(bOff[np] + kb));
        }

        #pragma unroll
        for (int ks = 0; ks < 16; ++ks) {
            const int cur = ks & 1;
            if (ks < 15) {
                const int nks   = ks + 1;
                const int nxt   = nks & 1;
                const uint32_t kb = (uint32_t)((nks & 3) * 32) + kbsel;
                const uint32_t aB = sb + OFF_A + (nks >> 2) * 8192;
                const uint32_t bB = sb + OFF_B + (nks >> 2) * 32768;
                #pragma unroll
                for (int mt = 0; mt < 2; ++mt) LDSM4(a[nxt][mt], aB + SWZ(aOff[mt] + kb));
                #pragma unroll
                for (int np = 0; np < 2; ++np) LDSM4(b[nxt][np], bB + SWZ(bOff[np] + kb));
            }
            #pragma unroll
            for (int mt = 0; mt < 2; ++mt)
                #pragma unroll
                for (int nt = 0; nt < 4; ++nt) {
                    const int np = nt >> 1, hl = nt & 1;
                    MMA_BF16(acc[mt][nt], a[cur][mt], b[cur][np][hl], b[cur][np][hl + 2]);
                }
        }

        // prefetch next meta-path's A (coalesced) to hide DRAM behind epilogue
        uint2 pf[8];
        if (m + 1 < NUM_M) loadA_regs(pf, homo, m + 1, N, n0, nv, wid, lane);

        // ---- epilogue on register accumulators ----
        float numr[2][2], sqr[2][2];
        #pragma unroll
        for (int mt = 0; mt < 2; ++mt)
            for (int h = 0; h < 2; ++h) { numr[mt][h] = 0.f; sqr[mt][h] = 0.f; }

        #pragma unroll
        for (int mt = 0; mt < 2; ++mt) {
            const int rowA = wm * 32 + mt * 16 + gid;
            const int rowB = rowA + 8;
            #pragma unroll
            for (int nt = 0; nt < 4; ++nt) {
                const int col = wn * 32 + nt * 8 + tig * 2;
                float2 b2 = *reinterpret_cast<const float2*>(&sbias[col]);
                float2 tA = __bfloat1622float2(tg2[rowA * (TGT_STRIDE / 2) + (col >> 1)]);
                float2 tB = __bfloat1622float2(tg2[rowB * (TGT_STRIDE / 2) + (col >> 1)]);
                float h0 = fast_tanh(acc[mt][nt][0] + b2.x);
                float h1 = fast_tanh(acc[mt][nt][1] + b2.y);
                float h2 = fast_tanh(acc[mt][nt][2] + b2.x);
                float h3 = fast_tanh(acc[mt][nt][3] + b2.y);
                numr[mt][0] = fmaf(h0, tA.x, numr[mt][0]);
                numr[mt][0] = fmaf(h1, tA.y, numr[mt][0]);
                sqr[mt][0]  = fmaf(h0, h0, sqr[mt][0]);
                sqr[mt][0]  = fmaf(h1, h1, sqr[mt][0]);
                numr[mt][1] = fmaf(h2, tB.x, numr[mt][1]);
                numr[mt][1] = fmaf(h3, tB.y, numr[mt][1]);
                sqr[mt][1]  = fmaf(h2, h2, sqr[mt][1]);
                sqr[mt][1]  = fmaf(h3, h3, sqr[mt][1]);
            }
        }
        #pragma unroll
        for (int mt = 0; mt < 2; ++mt)
            #pragma unroll
            for (int h = 0; h < 2; ++h) {
                numr[mt][h] += __shfl_xor_sync(0xffffffffu, numr[mt][h], 1);
                numr[mt][h] += __shfl_xor_sync(0xffffffffu, numr[mt][h], 2);
                sqr[mt][h]  += __shfl_xor_sync(0xffffffffu, sqr[mt][h], 1);
                sqr[mt][h]  += __shfl_xor_sync(0xffffffffu, sqr[mt][h], 2);
            }
        if (tig == 0) {
            #pragma unroll
            for (int mt = 0; mt < 2; ++mt)
                #pragma unroll
                for (int h = 0; h < 2; ++h) {
                    int row = wm * 32 + mt * 16 + h * 8 + gid;
                    srnum[row * 8 + wn] = numr[mt][h];
                    srsq[row * 8 + wn]  = sqr[mt][h];
                }
        }
        __syncthreads();   // A reads done by all warps; reductions visible

        if (m + 1 < NUM_M) storeA(pf, smem, wid, lane);
        if (tid < BM) {
            float num = 0.f, sq = 0.f;
            #pragma unroll
            for (int w = 0; w < 8; ++w) {
                num += srnum[tid * 8 + w];
                sq  += srsq[tid * 8 + w];
            }
            float hn = fmaxf(sqrtf(sq), 1e-8f);
            slogit[m * BM + tid] = num / (hn * stn[tid]);
        }
        __syncthreads();   // new A visible; red arrays free
    }

    // ---------------- softmax over meta-paths ----------------
    if (tid < BM) {
        float mx = -1e30f;
        #pragma unroll
        for (int m = 0; m < NUM_M; ++m) mx = fmaxf(mx, slogit[m * BM + tid]);
        float e[NUM_M], sum = 0.f;
        #pragma unroll
        for (int m = 0; m < NUM_M; ++m) {
            e[m] = __expf(slogit[m * BM + tid] - mx);
            sum += e[m];
        }
        float inv = 1.f / sum;
        #pragma unroll
        for (int m = 0; m < NUM_M; ++m) slogit[m * BM + tid] = e[m] * inv;
    }
    __syncthreads();

    // ---------------- weighted sum (f32) -> out ----------------
    for (int q = tid; q < BM * (DD / 4); q += NT) {
        int r  = q >> 6;
        int c4 = q & 63;
        if (r < nv) {
            float4 o = make_float4(0.f, 0.f, 0.f, 0.f);
            #pragma unroll
            for (int m = 0; m < NUM_M; ++m) {
                float a = slogit[m * BM + r];
                float4 v = reinterpret_cast<const float4*>(homo)
                               [((size_t)m * N + n0 + r) * (DD / 4) + c4];
                o.x = fmaf(a, v.x, o.x);
                o.y = fmaf(a, v.y, o.y);
                o.z = fmaf(a, v.z, o.z);
                o.w = fmaf(a, v.w, o.w);
            }
            reinterpret_cast<float4*>(out)[(size_t)(n0 + r) * (DD / 4) + c4] = o;
        }
    }
}

extern "C" void kernel_launch(void* const* d_in, const int* in_sizes, int n_in,
                              void* d_out, int out_size) {
    const int*   nodes = (const int*)  d_in[0];
    const float* homo  = (const float*)d_in[1];
    const float* W     = (const float*)d_in[2];
    const float* b     = (const float*)d_in[3];
    const float* oe    = (const float*)d_in[4];
    float* out = (float*)d_out;
    const int N = in_sizes[0];
    (void)n_in; (void)out_size;

    cudaFuncSetAttribute(hete_mma_kernel,
                         cudaFuncAttributeMaxDynamicSharedMemorySize, SMEM_SIZE);

    int grid = (N + BM - 1) / BM;
    hete_mma_kernel<<<grid, NT, SMEM_SIZE>>>(nodes, homo, W, b, oe, out, N);
}